// round 10
// baseline (speedup 1.0000x reference)
#include <cuda_runtime.h>
#include <cstdint>

// ---------------------------------------------------------------------------
// ChaoticLSTM: bs=64, seq=512, in=128, H=256, 4H=1024, T=512
//   Phase 1: xproj[32768][1024] = X[32768][128] @ Wi[128][1024] + B
//   Phase 2: recurrence, 8 clusters x 8 CTAs x 256 thr, 2 cols/thread,
//     two batch-groups pipelined per cluster (R9).
//     R10: handoff = direct per-dest DSMEM stores from ONE lane per dest
//     (32x st.shared::cluster.v4) + st.release step-stamp sentinel +
//     receiver ld.acquire spin. No bulk engine, no mbarrier in the loop.
// ---------------------------------------------------------------------------

typedef unsigned long long ull;

__device__ float g_xproj[32768u * 1024u];   // 128 MB scratch

__device__ __forceinline__ void fma2(ull& d, ull a, ull b) {
    asm("fma.rn.f32x2 %0, %1, %2, %0;" : "+l"(d) : "l"(a), "l"(b));
}
__device__ __forceinline__ ull splat2(float x) {
    ull r; asm("mov.b64 %0, {%1, %1};" : "=l"(r) : "f"(x)); return r;
}
__device__ __forceinline__ ull pack2(float a, float b) {
    ull r; asm("mov.b64 %0, {%1, %2};" : "=l"(r) : "f"(a), "f"(b)); return r;
}
__device__ __forceinline__ float2 unpack2(ull v) {
    float2 r; asm("mov.b64 {%0, %1}, %2;" : "=f"(r.x), "=f"(r.y) : "l"(v)); return r;
}
__device__ __forceinline__ float rcpf(float x) {
    float r; asm("rcp.approx.f32 %0, %1;" : "=f"(r) : "f"(x)); return r;
}
__device__ __forceinline__ uint32_t smem_u32(const void* p) {
    uint32_t a;
    asm("{ .reg .u64 t; cvta.to.shared.u64 t, %1; cvt.u32.u64 %0, t; }"
        : "=r"(a) : "l"(p));
    return a;
}

// ---------------------------------------------------------------------------
// Phase 1: xproj GEMM (unchanged).
// ---------------------------------------------------------------------------
__global__ __launch_bounds__(256) void xproj_kernel(const float* __restrict__ X,
                                                    const float* __restrict__ Wi,
                                                    const float* __restrict__ Bias) {
    __shared__ __align__(16) float As_t[32 * 68];
    __shared__ __align__(16) float Bs[32 * 64];

    const int tid = threadIdx.x;
    const int m0 = blockIdx.y * 64;
    const int n0 = blockIdx.x * 64;
    const int tm = tid >> 4, tn = tid & 15;

    ull acc[4][2];
#pragma unroll
    for (int i = 0; i < 4; ++i) { acc[i][0] = 0ull; acc[i][1] = 0ull; }

    const float4* X4  = (const float4*)X;
    const float4* Wi4 = (const float4*)Wi;

    for (int kt = 0; kt < 128; kt += 32) {
#pragma unroll
        for (int i = 0; i < 2; ++i) {
            int f = tid + i * 256;
            int row = f >> 3, kk4 = f & 7;
            float4 v = X4[(size_t)(m0 + row) * 32 + (kt >> 2) + kk4];
            As_t[(kk4 * 4 + 0) * 68 + row] = v.x;
            As_t[(kk4 * 4 + 1) * 68 + row] = v.y;
            As_t[(kk4 * 4 + 2) * 68 + row] = v.z;
            As_t[(kk4 * 4 + 3) * 68 + row] = v.w;
        }
#pragma unroll
        for (int i = 0; i < 2; ++i) {
            int f = tid + i * 256;
            int row = f >> 4, c4 = f & 15;
            *(float4*)(Bs + row * 64 + c4 * 4) =
                Wi4[(size_t)(kt + row) * 256 + (n0 >> 2) + c4];
        }
        __syncthreads();
#pragma unroll
        for (int kk = 0; kk < 32; ++kk) {
            float4 a4 = *(const float4*)(As_t + kk * 68 + tm * 4);
            ulonglong2 b2 = *(const ulonglong2*)(Bs + kk * 64 + tn * 4);
            ull s;
            s = splat2(a4.x); fma2(acc[0][0], s, b2.x); fma2(acc[0][1], s, b2.y);
            s = splat2(a4.y); fma2(acc[1][0], s, b2.x); fma2(acc[1][1], s, b2.y);
            s = splat2(a4.z); fma2(acc[2][0], s, b2.x); fma2(acc[2][1], s, b2.y);
            s = splat2(a4.w); fma2(acc[3][0], s, b2.x); fma2(acc[3][1], s, b2.y);
        }
        __syncthreads();
    }

    float4 bias = *(const float4*)(Bias + n0 + tn * 4);
#pragma unroll
    for (int i = 0; i < 4; ++i) {
        float2 p0 = unpack2(acc[i][0]);
        float2 p1 = unpack2(acc[i][1]);
        float4 o = make_float4(p0.x + bias.x, p0.y + bias.y,
                               p1.x + bias.z, p1.y + bias.w);
        *(float4*)(g_xproj + (size_t)(m0 + tm * 4 + i) * 1024 + n0 + tn * 4) = o;
    }
}

// ---------------------------------------------------------------------------
// Phase 2: dual-group pipelined recurrence, sentinel-store handoff.
//
// Thread map (as R7/R9): warp w (0..7); lane: s = lane>>3 (batch-in-group),
//   cl = lane&7, m = cl>>1, q = cl&1. Local h-dim j = w*4+m; koff = r*32+j;
//   columns = gates {2q, 2q+1} of dim j (shared wreg across both groups).
// Per group g: hbuf[g][2][8 x 132f] ping-pong, stage[g][2][128],
//   tags[g][2][8] step-stamps (init 0xFFFFFFFF).
// Handoff (group g, step t): bar split (warp g = observer) -> warp g lanes
//   0..7: lane d ships stage 512B to dest d's hbuf rank-r block (32x
//   st.shared::cluster.v4) then st.release stamp t into dest d's
//   tags[g][t&1][r]. Receiver at step t+1: lanes 0..7 spin ld.acquire on
//   tags[g][t&1][0..7]==t, syncwarp, read hbuf.
// ---------------------------------------------------------------------------
#define RSTRIDE 132
#define HBUFSZ  (8 * RSTRIDE)

__global__ __launch_bounds__(256, 1) __cluster_dims__(8, 1, 1)
void lstm_rec(const float* __restrict__ Wh, float* __restrict__ out) {
    __shared__ __align__(16) float hbuf[2][2][HBUFSZ];   // [group][buf]
    __shared__ __align__(16) float stage[2][2][128];     // [group][buf]
    __shared__ __align__(16) uint32_t tags[2][2][8];     // [group][buf][src]

    const int tid  = threadIdx.x;
    const int lane = tid & 31;
    const int w    = tid >> 5;           // 0..7
    const int s    = lane >> 3;          // batch index within group
    const int cl   = lane & 7;
    const int m    = cl >> 1;            // 0..3
    const int q    = cl & 1;             // gate-pair selector

    uint32_t rank;
    asm("mov.u32 %0, %%cluster_ctarank;" : "=r"(rank));
    const int r     = (int)rank;
    const int b0A   = (blockIdx.x >> 3) * 8;
    const int b0B   = b0A + 4;
    const int j     = w * 4 + m;
    const int koff  = r * 32 + j;
    const int colg0 = (2 * q) * 256 + koff;
    const int colg1 = (2 * q + 1) * 256 + koff;
    const int kbase = s * 64;

    // --- Wh slices -> registers (one-time, shared by both groups) ---
    ull wreg0[32], wreg1[32];
#pragma unroll
    for (int i = 0; i < 32; ++i) {
        const float* p0 = Wh + (size_t)(kbase + 2 * i) * 1024;
        const float* p1 = Wh + (size_t)(kbase + 2 * i + 1) * 1024;
        wreg0[i] = pack2(__ldg(p0 + colg0), __ldg(p1 + colg0));
        wreg1[i] = pack2(__ldg(p0 + colg1), __ldg(p1 + colg1));
    }

    // zero h buffers; poison tags
    for (int i = tid; i < 4 * HBUFSZ; i += 256) ((float*)hbuf)[i] = 0.0f;
    if (tid < 32) ((uint32_t*)tags)[tid] = 0xFFFFFFFFu;
    __syncthreads();
    asm volatile("barrier.cluster.arrive.aligned;" ::: "memory");
    asm volatile("barrier.cluster.wait.aligned;"   ::: "memory");

    // remote bases for sender lanes: warps 0/1, lane d < 8 -> dest CTA d
    const uint32_t hbase = smem_u32(hbuf);
    const uint32_t tbase = smem_u32(tags);
    uint32_t rem_hb = 0, rem_tg = 0;
    if (w < 2 && lane < 8) {
        asm("mapa.shared::cluster.u32 %0, %1, %2;" : "=r"(rem_hb) : "r"(hbase), "r"(lane));
        asm("mapa.shared::cluster.u32 %0, %1, %2;" : "=r"(rem_tg) : "r"(tbase), "r"(lane));
    }

    const float am0 = q ? 2.0f : 1.0f;
    const float om0 = q ? 2.0f : 1.0f;
    const float ob0 = q ? -1.0f : 0.0f;

    const bool cellw = (q == 0);
    const int  wslot = w * 16 + s * 4 + m;

    const float* xpA0 = g_xproj + (size_t)(b0A + s) * 512 * 1024 + colg0;
    const float* xpA1 = g_xproj + (size_t)(b0A + s) * 512 * 1024 + colg1;
    const float* xpB0 = g_xproj + (size_t)(b0B + s) * 512 * 1024 + colg0;
    const float* xpB1 = g_xproj + (size_t)(b0B + s) * 512 * 1024 + colg1;
    float* outA = out + (size_t)(b0A + s) * 512 * 256 + koff;
    float* outB = out + (size_t)(b0B + s) * 512 * 256 + koff;

    float xcA0 = __ldg(xpA0), xcA1 = __ldg(xpA1);
    float xcB0 = __ldg(xpB0), xcB1 = __ldg(xpB1);
    float creA = 0.0f, creB = 0.0f, hlA = 0.0f, hlB = 0.0f;

    // ---- per-group dot + cell ----
    auto dot_cell = [&](const float* hb, float xp0, float xp1,
                        float& cre) -> float {
        ull A00 = 0, A01 = 0, A02 = 0, A03 = 0;
        ull A10 = 0, A11 = 0, A12 = 0, A13 = 0;
#pragma unroll
        for (int rr = 0; rr < 2; ++rr) {
            const float* rbase = hb + (2 * s + rr) * RSTRIDE;
#pragma unroll
            for (int j4 = 0; j4 < 8; ++j4) {
                const float* qp = rbase + j4 * 16;
                ulonglong2 v0 = *(const ulonglong2*)(qp + 0);
                ulonglong2 v1 = *(const ulonglong2*)(qp + 4);
                ulonglong2 v2 = *(const ulonglong2*)(qp + 8);
                ulonglong2 v3 = *(const ulonglong2*)(qp + 12);
                const int iw = rr * 16 + j4 * 2;
                fma2(A00, wreg0[iw], v0.x); fma2(A00, wreg0[iw + 1], v0.y);
                fma2(A01, wreg0[iw], v1.x); fma2(A01, wreg0[iw + 1], v1.y);
                fma2(A02, wreg0[iw], v2.x); fma2(A02, wreg0[iw + 1], v2.y);
                fma2(A03, wreg0[iw], v3.x); fma2(A03, wreg0[iw + 1], v3.y);
                fma2(A10, wreg1[iw], v0.x); fma2(A10, wreg1[iw + 1], v0.y);
                fma2(A11, wreg1[iw], v1.x); fma2(A11, wreg1[iw + 1], v1.y);
                fma2(A12, wreg1[iw], v2.x); fma2(A12, wreg1[iw + 1], v2.y);
                fma2(A13, wreg1[iw], v3.x); fma2(A13, wreg1[iw + 1], v3.y);
            }
        }
        float2 p;
        float d00, d01, d02, d03, d10, d11, d12, d13;
        p = unpack2(A00); d00 = p.x + p.y;
        p = unpack2(A01); d01 = p.x + p.y;
        p = unpack2(A02); d02 = p.x + p.y;
        p = unpack2(A03); d03 = p.x + p.y;
        p = unpack2(A10); d10 = p.x + p.y;
        p = unpack2(A11); d11 = p.x + p.y;
        p = unpack2(A12); d12 = p.x + p.y;
        p = unpack2(A13); d13 = p.x + p.y;

        d00 += __shfl_xor_sync(0xffffffffu, d00, 8);
        d01 += __shfl_xor_sync(0xffffffffu, d01, 8);
        d02 += __shfl_xor_sync(0xffffffffu, d02, 8);
        d03 += __shfl_xor_sync(0xffffffffu, d03, 8);
        d10 += __shfl_xor_sync(0xffffffffu, d10, 8);
        d11 += __shfl_xor_sync(0xffffffffu, d11, 8);
        d12 += __shfl_xor_sync(0xffffffffu, d12, 8);
        d13 += __shfl_xor_sync(0xffffffffu, d13, 8);
        d00 += __shfl_xor_sync(0xffffffffu, d00, 16);
        d01 += __shfl_xor_sync(0xffffffffu, d01, 16);
        d02 += __shfl_xor_sync(0xffffffffu, d02, 16);
        d03 += __shfl_xor_sync(0xffffffffu, d03, 16);
        d10 += __shfl_xor_sync(0xffffffffu, d10, 16);
        d11 += __shfl_xor_sync(0xffffffffu, d11, 16);
        d12 += __shfl_xor_sync(0xffffffffu, d12, 16);
        d13 += __shfl_xor_sync(0xffffffffu, d13, 16);

        float ds0 = (s == 0) ? d00 : (s == 1) ? d01 : (s == 2) ? d02 : d03;
        float ds1 = (s == 0) ? d10 : (s == 1) ? d11 : (s == 2) ? d12 : d13;
        float gx0 = xp0 + ds0;
        float gx1 = xp1 + ds1;

        float u0 = __expf(-am0 * gx0);
        float e0 = fmaf(rcpf(1.0f + u0), om0, ob0);
        float u1 = __expf(-gx1);
        float e1 = rcpf(1.0f + u1);

        float gg = __shfl_xor_sync(0xffffffffu, e0, 1);
        float oo = __shfl_xor_sync(0xffffffffu, e1, 1);

        float hn = 0.0f;
        if (cellw) {
            cre = fmaf(e1, cre, e0 * gg);
            float u2 = __expf(-2.0f * cre);
            float th = (1.0f - u2) * rcpf(1.0f + u2);
            hn = oo * th;
        }
        return hn;
    };

    // receiver: spin until all 8 src ranks stamped step u for group g
    auto wait_tags = [&](int g, int u) {
        if (lane < 8) {
            uint32_t ta = tbase + (uint32_t)(((g * 2 + (u & 1)) * 8 + lane) * 4);
            uint32_t expv = (uint32_t)u;
            uint32_t v;
            do {
                asm volatile("ld.acquire.cluster.shared::cta.b32 %0, [%1];"
                             : "=r"(v) : "r"(ta) : "memory");
            } while (v != expv);
        }
        __syncwarp();
    };

    // sender: warp g, lanes 0..7; lane d ships 512B + stamp to dest d
    auto send_group = [&](int g, int t) {
        if (lane < 8) {
            const float4* sp = (const float4*)&stage[g][t & 1][0];
            uint32_t dst = rem_hb +
                (uint32_t)(((g * 2 + (t & 1)) * HBUFSZ + r * RSTRIDE) * 4);
#pragma unroll
            for (int i = 0; i < 32; ++i) {
                float4 v = sp[i];
                asm volatile("st.shared::cluster.v4.f32 [%0], {%1,%2,%3,%4};"
                             :: "r"(dst + (uint32_t)(i * 16)),
                                "f"(v.x), "f"(v.y), "f"(v.z), "f"(v.w)
                             : "memory");
            }
            uint32_t tga = rem_tg +
                (uint32_t)(((g * 2 + (t & 1)) * 8 + r) * 4);
            asm volatile("st.release.cluster.shared::cluster.u32 [%0], %1;"
                         :: "r"(tga), "r"((uint32_t)t) : "memory");
        }
    };

#pragma unroll 1
    for (int t = 0; t < 512; ++t) {
        // ================= group A =================
        if (t > 0) wait_tags(0, t - 1);
        {
            const float* hb = (const float*)hbuf + ((t + 1) & 1) * HBUFSZ;
            float hn = dot_cell(hb, xcA0, xcA1, creA);
            if (cellw) { hlA = hn; stage[0][t & 1][wslot] = hn; }

            if (w == 0) asm volatile("bar.sync 1, 256;" ::: "memory");
            else        asm volatile("bar.arrive 1, 256;" ::: "memory");

            if (w == 0 && t < 511) send_group(0, t);

            if (cellw) outA[(size_t)t * 256] = hn;
            if (t < 511) { xcA0 = __ldg(xpA0 + (size_t)(t + 1) * 1024);
                           xcA1 = __ldg(xpA1 + (size_t)(t + 1) * 1024); }
        }

        // ================= group B =================
        if (t > 0) wait_tags(1, t - 1);
        {
            const float* hb = (const float*)hbuf + (2 + ((t + 1) & 1)) * HBUFSZ;
            float hn = dot_cell(hb, xcB0, xcB1, creB);
            if (cellw) { hlB = hn; stage[1][t & 1][wslot] = hn; }

            if (w == 1) asm volatile("bar.sync 2, 256;" ::: "memory");
            else        asm volatile("bar.arrive 2, 256;" ::: "memory");

            if (w == 1 && t < 511) send_group(1, t);

            if (cellw) outB[(size_t)t * 256] = hn;
            if (t < 511) { xcB0 = __ldg(xpB0 + (size_t)(t + 1) * 1024);
                           xcB1 = __ldg(xpB1 + (size_t)(t + 1) * 1024); }
        }
    }

    if (cellw) {
        out[8388608u + (size_t)(b0A + s) * 256 + koff]          = hlA;
        out[8388608u + 16384u + (size_t)(b0A + s) * 256 + koff] = creA;
        out[8388608u + (size_t)(b0B + s) * 256 + koff]          = hlB;
        out[8388608u + 16384u + (size_t)(b0B + s) * 256 + koff] = creB;
    }
}

// ---------------------------------------------------------------------------
extern "C" void kernel_launch(void* const* d_in, const int* in_sizes, int n_in,
                              void* d_out, int out_size) {
    const float* x  = nullptr;   // 64*512*128 = 4194304
    const float* Wi = nullptr;   // 128*1024   = 131072
    const float* Wh = nullptr;   // 256*1024   = 262144
    const float* Bb = nullptr;   // 1024
    for (int i = 0; i < n_in; ++i) {
        switch (in_sizes[i]) {
            case 4194304: x  = (const float*)d_in[i]; break;
            case 131072:  Wi = (const float*)d_in[i]; break;
            case 262144:  Wh = (const float*)d_in[i]; break;
            case 1024:    Bb = (const float*)d_in[i]; break;
            default: break;
        }
    }
    float* out = (float*)d_out;
    (void)out_size;

    xproj_kernel<<<dim3(16, 512), 256>>>(x, Wi, Bb);
    lstm_rec<<<64, 256>>>(Wh, out);
}

// round 11
// speedup vs baseline: 1.0369x; 1.0369x over previous
#include <cuda_runtime.h>
#include <cstdint>

// ---------------------------------------------------------------------------
// ChaoticLSTM: bs=64, seq=512, in=128, H=256, 4H=1024, T=512
// R11: ONE fused 128-block cluster launch.
//   blocks 0..63   : R9 recurrence (8 clusters x 8 CTAs, 2 groups pipelined,
//                    bulk+tx-mbarrier handoff), B-send race fixed (warp 1).
//   blocks 64..127 : xproj workers, chunk-major tile order, publishing
//                    per-chunk completion counters that the recurrence
//                    gates its xp prefetch on (once per 64 steps).
// A tiny reset kernel zeroes the counters each launch (replay-safe).
// ---------------------------------------------------------------------------

typedef unsigned long long ull;

__device__ float    g_xproj[32768u * 1024u];   // 128 MB scratch
__device__ unsigned g_cnt[8];                  // per-chunk finished-tile count

__device__ __forceinline__ void fma2(ull& d, ull a, ull b) {
    asm("fma.rn.f32x2 %0, %1, %2, %0;" : "+l"(d) : "l"(a), "l"(b));
}
__device__ __forceinline__ ull splat2(float x) {
    ull r; asm("mov.b64 %0, {%1, %1};" : "=l"(r) : "f"(x)); return r;
}
__device__ __forceinline__ ull pack2(float a, float b) {
    ull r; asm("mov.b64 %0, {%1, %2};" : "=l"(r) : "f"(a), "f"(b)); return r;
}
__device__ __forceinline__ float2 unpack2(ull v) {
    float2 r; asm("mov.b64 {%0, %1}, %2;" : "=f"(r.x), "=f"(r.y) : "l"(v)); return r;
}
__device__ __forceinline__ float rcpf(float x) {
    float r; asm("rcp.approx.f32 %0, %1;" : "=f"(r) : "f"(x)); return r;
}
__device__ __forceinline__ uint32_t smem_u32(const void* p) {
    uint32_t a;
    asm("{ .reg .u64 t; cvta.to.shared.u64 t, %1; cvt.u32.u64 %0, t; }"
        : "=r"(a) : "l"(p));
    return a;
}

__global__ void reset_kernel() {
    if (threadIdx.x < 8) g_cnt[threadIdx.x] = 0u;
}

#define RSTRIDE 132
#define HBUFSZ  (8 * RSTRIDE)
// smem pool: rec needs 4*HBUFSZ*4 + 512*4 = 18944 B; xproj needs 16896 B.
#define POOLSZ  18944

__global__ __launch_bounds__(256, 1) __cluster_dims__(8, 1, 1)
void lstm_fused(const float* __restrict__ X,  const float* __restrict__ Wi,
                const float* __restrict__ Bias, const float* __restrict__ Wh,
                float* __restrict__ out) {
    __shared__ __align__(16) char smpool[POOLSZ];
    __shared__ __align__(8)  ull  mbars[4];

    const int tid = threadIdx.x;

    // =========================================================================
    // xproj workers: blocks 64..127. Tile = 64 t-rows x 64 n-cols of one batch.
    // Chunk-major order: tile id = c*1024 + round*64 + wkr.
    // =========================================================================
    if (blockIdx.x >= 64) {
        float* As_t = (float*)smpool;       // 32*68 floats
        float* Bs   = As_t + 32 * 68;       // 32*64 floats
        const int wkr = blockIdx.x - 64;
        const int tm = tid >> 4, tn = tid & 15;
        const float4* X4  = (const float4*)X;
        const float4* Wi4 = (const float4*)Wi;

        for (int it = 0; it < 128; ++it) {
            const int tile = it * 64 + wkr;
            const int c  = tile >> 10;           // chunk 0..7
            const int jb = tile & 1023;
            const int b  = jb >> 4, nx = jb & 15;
            const int m0 = b * 512 + c * 64;
            const int n0 = nx * 64;

            ull acc[4][2];
#pragma unroll
            for (int i = 0; i < 4; ++i) { acc[i][0] = 0ull; acc[i][1] = 0ull; }

            for (int kt = 0; kt < 128; kt += 32) {
#pragma unroll
                for (int i = 0; i < 2; ++i) {
                    int f = tid + i * 256;
                    int row = f >> 3, kk4 = f & 7;
                    float4 v = X4[(size_t)(m0 + row) * 32 + (kt >> 2) + kk4];
                    As_t[(kk4 * 4 + 0) * 68 + row] = v.x;
                    As_t[(kk4 * 4 + 1) * 68 + row] = v.y;
                    As_t[(kk4 * 4 + 2) * 68 + row] = v.z;
                    As_t[(kk4 * 4 + 3) * 68 + row] = v.w;
                }
#pragma unroll
                for (int i = 0; i < 2; ++i) {
                    int f = tid + i * 256;
                    int row = f >> 4, c4 = f & 15;
                    *(float4*)(Bs + row * 64 + c4 * 4) =
                        Wi4[(size_t)(kt + row) * 256 + (n0 >> 2) + c4];
                }
                __syncthreads();
#pragma unroll
                for (int kk = 0; kk < 32; ++kk) {
                    float4 a4 = *(const float4*)(As_t + kk * 68 + tm * 4);
                    ulonglong2 b2 = *(const ulonglong2*)(Bs + kk * 64 + tn * 4);
                    ull s;
                    s = splat2(a4.x); fma2(acc[0][0], s, b2.x); fma2(acc[0][1], s, b2.y);
                    s = splat2(a4.y); fma2(acc[1][0], s, b2.x); fma2(acc[1][1], s, b2.y);
                    s = splat2(a4.z); fma2(acc[2][0], s, b2.x); fma2(acc[2][1], s, b2.y);
                    s = splat2(a4.w); fma2(acc[3][0], s, b2.x); fma2(acc[3][1], s, b2.y);
                }
                __syncthreads();
            }

            float4 bias = *(const float4*)(Bias + n0 + tn * 4);
#pragma unroll
            for (int i = 0; i < 4; ++i) {
                float2 p0 = unpack2(acc[i][0]);
                float2 p1 = unpack2(acc[i][1]);
                float4 o = make_float4(p0.x + bias.x, p0.y + bias.y,
                                       p1.x + bias.z, p1.y + bias.w);
                *(float4*)(g_xproj + (size_t)(m0 + tm * 4 + i) * 1024 + n0 + tn * 4) = o;
            }

            __threadfence();       // my stores visible device-wide
            __syncthreads();       // whole block done with this tile
            if (tid == 0) atomicAdd(&g_cnt[c], 1u);
        }
        return;
    }

    // =========================================================================
    // Recurrence: blocks 0..63 (R9, with B-send issued by warp 1, xp gated
    // on chunk counters).
    // =========================================================================
    float* hbufp  = (float*)smpool;          // [group*2+buf][HBUFSZ]
    float* stagep = hbufp + 4 * HBUFSZ;      // [group*2+buf][128]

    const int lane = tid & 31;
    const int w    = tid >> 5;
    const int s    = lane >> 3;
    const int cl   = lane & 7;
    const int m    = cl >> 1;
    const int q    = cl & 1;

    uint32_t rank;
    asm("mov.u32 %0, %%cluster_ctarank;" : "=r"(rank));
    const int r     = (int)rank;
    const int b0A   = (blockIdx.x >> 3) * 8;
    const int b0B   = b0A + 4;
    const int j     = w * 4 + m;
    const int koff  = r * 32 + j;
    const int colg0 = (2 * q) * 256 + koff;
    const int colg1 = (2 * q + 1) * 256 + koff;
    const int kbase = s * 64;

    ull wreg0[32], wreg1[32];
#pragma unroll
    for (int i = 0; i < 32; ++i) {
        const float* p0 = Wh + (size_t)(kbase + 2 * i) * 1024;
        const float* p1 = Wh + (size_t)(kbase + 2 * i + 1) * 1024;
        wreg0[i] = pack2(__ldg(p0 + colg0), __ldg(p1 + colg0));
        wreg1[i] = pack2(__ldg(p0 + colg1), __ldg(p1 + colg1));
    }

    for (int i = tid; i < 4 * HBUFSZ; i += 256) hbufp[i] = 0.0f;
    const uint32_t lmb = smem_u32(mbars);
    if (tid == 0) {
#pragma unroll
        for (int i = 0; i < 4; ++i)
            asm volatile("mbarrier.init.shared.b64 [%0], 1;"
                         :: "r"(lmb + 8 * i) : "memory");
    }
    __syncthreads();
    asm volatile("barrier.cluster.arrive.aligned;" ::: "memory");
    asm volatile("barrier.cluster.wait.aligned;"   ::: "memory");

    // remote addresses for sender lanes of warps 0 (group A) and 1 (group B)
    const uint32_t hbase = smem_u32(hbufp);
    const uint32_t sbase = smem_u32(stagep);
    uint32_t rem_h = 0, rem_m = 0;
    if (w < 2 && lane < 8) {
        asm("mapa.shared::cluster.u32 %0, %1, %2;" : "=r"(rem_h) : "r"(hbase), "r"(lane));
        asm("mapa.shared::cluster.u32 %0, %1, %2;" : "=r"(rem_m) : "r"(lmb),   "r"(lane));
    }

    const float am0 = q ? 2.0f : 1.0f;
    const float om0 = q ? 2.0f : 1.0f;
    const float ob0 = q ? -1.0f : 0.0f;

    const bool cellw = (q == 0);
    const int  wslot = w * 16 + s * 4 + m;

    const float* xpA0 = g_xproj + (size_t)(b0A + s) * 512 * 1024 + colg0;
    const float* xpA1 = g_xproj + (size_t)(b0A + s) * 512 * 1024 + colg1;
    const float* xpB0 = g_xproj + (size_t)(b0B + s) * 512 * 1024 + colg0;
    const float* xpB1 = g_xproj + (size_t)(b0B + s) * 512 * 1024 + colg1;
    float* outA = out + (size_t)(b0A + s) * 512 * 256 + koff;
    float* outB = out + (size_t)(b0B + s) * 512 * 256 + koff;

    // chunk gate: spin until all 1024 tiles of chunk c are published
    auto wait_chunk = [&](int c) {
        uint32_t v;
        do {
            asm volatile("ld.acquire.gpu.u32 %0, [%1];"
                         : "=r"(v) : "l"(&g_cnt[c]) : "memory");
        } while (v < 1024u);
    };

    wait_chunk(0);
    float xcA0 = __ldg(xpA0), xcA1 = __ldg(xpA1);
    float xcB0 = __ldg(xpB0), xcB1 = __ldg(xpB1);
    float creA = 0.0f, creB = 0.0f, hlA = 0.0f, hlB = 0.0f;

    auto dot_cell = [&](const float* hb, float xp0, float xp1,
                        float& cre) -> float {
        ull A00 = 0, A01 = 0, A02 = 0, A03 = 0;
        ull A10 = 0, A11 = 0, A12 = 0, A13 = 0;
#pragma unroll
        for (int rr = 0; rr < 2; ++rr) {
            const float* rbase = hb + (2 * s + rr) * RSTRIDE;
#pragma unroll
            for (int j4 = 0; j4 < 8; ++j4) {
                const float* qp = rbase + j4 * 16;
                ulonglong2 v0 = *(const ulonglong2*)(qp + 0);
                ulonglong2 v1 = *(const ulonglong2*)(qp + 4);
                ulonglong2 v2 = *(const ulonglong2*)(qp + 8);
                ulonglong2 v3 = *(const ulonglong2*)(qp + 12);
                const int iw = rr * 16 + j4 * 2;
                fma2(A00, wreg0[iw], v0.x); fma2(A00, wreg0[iw + 1], v0.y);
                fma2(A01, wreg0[iw], v1.x); fma2(A01, wreg0[iw + 1], v1.y);
                fma2(A02, wreg0[iw], v2.x); fma2(A02, wreg0[iw + 1], v2.y);
                fma2(A03, wreg0[iw], v3.x); fma2(A03, wreg0[iw + 1], v3.y);
                fma2(A10, wreg1[iw], v0.x); fma2(A10, wreg1[iw + 1], v0.y);
                fma2(A11, wreg1[iw], v1.x); fma2(A11, wreg1[iw + 1], v1.y);
                fma2(A12, wreg1[iw], v2.x); fma2(A12, wreg1[iw + 1], v2.y);
                fma2(A13, wreg1[iw], v3.x); fma2(A13, wreg1[iw + 1], v3.y);
            }
        }
        float2 p;
        float d00, d01, d02, d03, d10, d11, d12, d13;
        p = unpack2(A00); d00 = p.x + p.y;
        p = unpack2(A01); d01 = p.x + p.y;
        p = unpack2(A02); d02 = p.x + p.y;
        p = unpack2(A03); d03 = p.x + p.y;
        p = unpack2(A10); d10 = p.x + p.y;
        p = unpack2(A11); d11 = p.x + p.y;
        p = unpack2(A12); d12 = p.x + p.y;
        p = unpack2(A13); d13 = p.x + p.y;

        d00 += __shfl_xor_sync(0xffffffffu, d00, 8);
        d01 += __shfl_xor_sync(0xffffffffu, d01, 8);
        d02 += __shfl_xor_sync(0xffffffffu, d02, 8);
        d03 += __shfl_xor_sync(0xffffffffu, d03, 8);
        d10 += __shfl_xor_sync(0xffffffffu, d10, 8);
        d11 += __shfl_xor_sync(0xffffffffu, d11, 8);
        d12 += __shfl_xor_sync(0xffffffffu, d12, 8);
        d13 += __shfl_xor_sync(0xffffffffu, d13, 8);
        d00 += __shfl_xor_sync(0xffffffffu, d00, 16);
        d01 += __shfl_xor_sync(0xffffffffu, d01, 16);
        d02 += __shfl_xor_sync(0xffffffffu, d02, 16);
        d03 += __shfl_xor_sync(0xffffffffu, d03, 16);
        d10 += __shfl_xor_sync(0xffffffffu, d10, 16);
        d11 += __shfl_xor_sync(0xffffffffu, d11, 16);
        d12 += __shfl_xor_sync(0xffffffffu, d12, 16);
        d13 += __shfl_xor_sync(0xffffffffu, d13, 16);

        float ds0 = (s == 0) ? d00 : (s == 1) ? d01 : (s == 2) ? d02 : d03;
        float ds1 = (s == 0) ? d10 : (s == 1) ? d11 : (s == 2) ? d12 : d13;
        float gx0 = xp0 + ds0;
        float gx1 = xp1 + ds1;

        float u0 = __expf(-am0 * gx0);
        float e0 = fmaf(rcpf(1.0f + u0), om0, ob0);
        float u1 = __expf(-gx1);
        float e1 = rcpf(1.0f + u1);

        float gg = __shfl_xor_sync(0xffffffffu, e0, 1);
        float oo = __shfl_xor_sync(0xffffffffu, e1, 1);

        float hn = 0.0f;
        if (cellw) {
            cre = fmaf(e1, cre, e0 * gg);
            float u2 = __expf(-2.0f * cre);
            float th = (1.0f - u2) * rcpf(1.0f + u2);
            hn = oo * th;
        }
        return hn;
    };

    auto wait_mbar = [&](int g, int u) {
        uint32_t mw = lmb + (uint32_t)((g * 2 + (u & 1)) << 3);
        uint32_t pr = (uint32_t)((u >> 1) & 1);
        asm volatile(
            "{\n\t.reg .pred P;\n"
            "W_%=:\n\t"
            "mbarrier.try_wait.parity.acquire.cta.shared::cta.b64 P, [%0], %1, 0x989680;\n\t"
            "@P bra.uni D_%=;\n\t"
            "bra.uni W_%=;\n\t"
            "D_%=:\n\t}"
            :: "r"(mw), "r"(pr) : "memory");
    };

    auto send_group = [&](int g, int t) {   // caller gates on warp & lane
        asm volatile("fence.proxy.async.shared::cta;" ::: "memory");
        uint32_t idx = (uint32_t)(g * 2 + (t & 1));
        uint32_t src = sbase + idx * 512u;
        uint32_t dst = rem_h + (uint32_t)((idx * HBUFSZ + r * RSTRIDE) * 4);
        uint32_t mba = rem_m + (idx << 3);
        asm volatile(
            "cp.async.bulk.shared::cluster.shared::cta.mbarrier::complete_tx::bytes "
            "[%0], [%1], %2, [%3];"
            :: "r"(dst), "r"(src), "r"(512u), "r"(mba) : "memory");
    };

#pragma unroll 1
    for (int t = 0; t < 512; ++t) {
        // ================= group A =================
        if (t > 0) wait_mbar(0, t - 1);
        if (tid == 0 && t < 511) {
            uint32_t ma = lmb + (uint32_t)((t & 1) << 3);
            asm volatile("mbarrier.arrive.expect_tx.shared.b64 _, [%0], %1;"
                         :: "r"(ma), "r"(4096u) : "memory");
        }
        {
            const float* hb = hbufp + ((t + 1) & 1) * HBUFSZ;
            float hn = dot_cell(hb, xcA0, xcA1, creA);
            if (cellw) { hlA = hn; stagep[(t & 1) * 128 + wslot] = hn; }

            if (w == 0) asm volatile("bar.sync 1, 256;" ::: "memory");
            else        asm volatile("bar.arrive 1, 256;" ::: "memory");

            if (t < 511 && w == 0 && lane < 8) send_group(0, t);

            if (cellw) outA[(size_t)t * 256] = hn;
            if (t < 511) {
                if (((t + 1) & 63) == 0) wait_chunk((t + 1) >> 6);
                xcA0 = __ldg(xpA0 + (size_t)(t + 1) * 1024);
                xcA1 = __ldg(xpA1 + (size_t)(t + 1) * 1024);
            }
        }

        // ================= group B =================
        if (t > 0) wait_mbar(1, t - 1);
        if (tid == 0 && t < 511) {
            uint32_t ma = lmb + (uint32_t)((2 + (t & 1)) << 3);
            asm volatile("mbarrier.arrive.expect_tx.shared.b64 _, [%0], %1;"
                         :: "r"(ma), "r"(4096u) : "memory");
        }
        {
            const float* hb = hbufp + (2 + ((t + 1) & 1)) * HBUFSZ;
            float hn = dot_cell(hb, xcB0, xcB1, creB);
            if (cellw) { hlB = hn; stagep[(2 + (t & 1)) * 128 + wslot] = hn; }

            if (w == 1) asm volatile("bar.sync 2, 256;" ::: "memory");
            else        asm volatile("bar.arrive 2, 256;" ::: "memory");

            if (t < 511 && w == 1 && lane < 8) send_group(1, t);

            if (cellw) outB[(size_t)t * 256] = hn;
            if (t < 511) {
                xcB0 = __ldg(xpB0 + (size_t)(t + 1) * 1024);
                xcB1 = __ldg(xpB1 + (size_t)(t + 1) * 1024);
            }
        }
    }

    if (cellw) {
        out[8388608u + (size_t)(b0A + s) * 256 + koff]          = hlA;
        out[8388608u + 16384u + (size_t)(b0A + s) * 256 + koff] = creA;
        out[8388608u + (size_t)(b0B + s) * 256 + koff]          = hlB;
        out[8388608u + 16384u + (size_t)(b0B + s) * 256 + koff] = creB;
    }
}

// ---------------------------------------------------------------------------
extern "C" void kernel_launch(void* const* d_in, const int* in_sizes, int n_in,
                              void* d_out, int out_size) {
    const float* x  = nullptr;   // 64*512*128 = 4194304
    const float* Wi = nullptr;   // 128*1024   = 131072
    const float* Wh = nullptr;   // 256*1024   = 262144
    const float* Bb = nullptr;   // 1024
    for (int i = 0; i < n_in; ++i) {
        switch (in_sizes[i]) {
            case 4194304: x  = (const float*)d_in[i]; break;
            case 131072:  Wi = (const float*)d_in[i]; break;
            case 262144:  Wh = (const float*)d_in[i]; break;
            case 1024:    Bb = (const float*)d_in[i]; break;
            default: break;
        }
    }
    float* out = (float*)d_out;
    (void)out_size;

    reset_kernel<<<1, 32>>>();
    lstm_fused<<<128, 256>>>(x, Wi, Bb, Wh, out);
}

// round 12
// speedup vs baseline: 1.4836x; 1.4309x over previous
#include <cuda_runtime.h>
#include <cstdint>

// ---------------------------------------------------------------------------
// ChaoticLSTM: bs=64, seq=512, in=128, H=256, 4H=1024, T=512
// R12: revert to the R9 two-kernel split (fusion regressed), with:
//   - xproj retiled to 64Mx128N (thread tile 4x8): halves smem-wavefront
//     cost per FLOP (the measured xproj bound).
//   - rec = R9 structure + B-send race fix (B sends from warp 1, which
//     bar.syncs barrier 2).
// ---------------------------------------------------------------------------

typedef unsigned long long ull;

__device__ float g_xproj[32768u * 1024u];   // 128 MB scratch

__device__ __forceinline__ void fma2(ull& d, ull a, ull b) {
    asm("fma.rn.f32x2 %0, %1, %2, %0;" : "+l"(d) : "l"(a), "l"(b));
}
__device__ __forceinline__ ull splat2(float x) {
    ull r; asm("mov.b64 %0, {%1, %1};" : "=l"(r) : "f"(x)); return r;
}
__device__ __forceinline__ ull pack2(float a, float b) {
    ull r; asm("mov.b64 %0, {%1, %2};" : "=l"(r) : "f"(a), "f"(b)); return r;
}
__device__ __forceinline__ float2 unpack2(ull v) {
    float2 r; asm("mov.b64 {%0, %1}, %2;" : "=f"(r.x), "=f"(r.y) : "l"(v)); return r;
}
__device__ __forceinline__ float rcpf(float x) {
    float r; asm("rcp.approx.f32 %0, %1;" : "=f"(r) : "f"(x)); return r;
}
__device__ __forceinline__ uint32_t smem_u32(const void* p) {
    uint32_t a;
    asm("{ .reg .u64 t; cvta.to.shared.u64 t, %1; cvt.u32.u64 %0, t; }"
        : "=r"(a) : "l"(p));
    return a;
}

// ---------------------------------------------------------------------------
// Phase 1: xproj GEMM, 64M x 128N block tile, 4x8 thread tile.
// grid = (8 n-tiles, 512 m-tiles), 256 threads.
// ---------------------------------------------------------------------------
__global__ __launch_bounds__(256) void xproj_kernel(const float* __restrict__ X,
                                                    const float* __restrict__ Wi,
                                                    const float* __restrict__ Bias) {
    __shared__ __align__(16) float As_t[32 * 68];    // [k][m], padded
    __shared__ __align__(16) float Bs[32 * 128];     // [k][n]

    const int tid = threadIdx.x;
    const int m0 = blockIdx.y * 64;
    const int n0 = blockIdx.x * 128;
    const int tm = tid >> 4, tn = tid & 15;

    ull acc[4][4];
#pragma unroll
    for (int i = 0; i < 4; ++i)
#pragma unroll
        for (int jj = 0; jj < 4; ++jj) acc[i][jj] = 0ull;

    const float4* X4  = (const float4*)X;
    const float4* Wi4 = (const float4*)Wi;

    for (int kt = 0; kt < 128; kt += 32) {
        // A: 64 rows x 32 k -> transposed smem (512 float4, 2/thread)
#pragma unroll
        for (int i = 0; i < 2; ++i) {
            int f = tid + i * 256;
            int row = f >> 3, kk4 = f & 7;
            float4 v = X4[(size_t)(m0 + row) * 32 + (kt >> 2) + kk4];
            As_t[(kk4 * 4 + 0) * 68 + row] = v.x;
            As_t[(kk4 * 4 + 1) * 68 + row] = v.y;
            As_t[(kk4 * 4 + 2) * 68 + row] = v.z;
            As_t[(kk4 * 4 + 3) * 68 + row] = v.w;
        }
        // B: 32 k-rows x 128 n (1024 float4, 4/thread)
#pragma unroll
        for (int i = 0; i < 4; ++i) {
            int f = tid + i * 256;
            int row = f >> 5, c4 = f & 31;
            *(float4*)(Bs + row * 128 + c4 * 4) =
                Wi4[(size_t)(kt + row) * 256 + (n0 >> 2) + c4];
        }
        __syncthreads();
#pragma unroll
        for (int kk = 0; kk < 32; ++kk) {
            float4 a4 = *(const float4*)(As_t + kk * 68 + tm * 4);
            ulonglong2 b0 = *(const ulonglong2*)(Bs + kk * 128 + tn * 8);
            ulonglong2 b1 = *(const ulonglong2*)(Bs + kk * 128 + tn * 8 + 4);
            ull s;
            s = splat2(a4.x);
            fma2(acc[0][0], s, b0.x); fma2(acc[0][1], s, b0.y);
            fma2(acc[0][2], s, b1.x); fma2(acc[0][3], s, b1.y);
            s = splat2(a4.y);
            fma2(acc[1][0], s, b0.x); fma2(acc[1][1], s, b0.y);
            fma2(acc[1][2], s, b1.x); fma2(acc[1][3], s, b1.y);
            s = splat2(a4.z);
            fma2(acc[2][0], s, b0.x); fma2(acc[2][1], s, b0.y);
            fma2(acc[2][2], s, b1.x); fma2(acc[2][3], s, b1.y);
            s = splat2(a4.w);
            fma2(acc[3][0], s, b0.x); fma2(acc[3][1], s, b0.y);
            fma2(acc[3][2], s, b1.x); fma2(acc[3][3], s, b1.y);
        }
        __syncthreads();
    }

    float4 bias0 = *(const float4*)(Bias + n0 + tn * 8);
    float4 bias1 = *(const float4*)(Bias + n0 + tn * 8 + 4);
#pragma unroll
    for (int i = 0; i < 4; ++i) {
        float2 p0 = unpack2(acc[i][0]);
        float2 p1 = unpack2(acc[i][1]);
        float2 p2 = unpack2(acc[i][2]);
        float2 p3 = unpack2(acc[i][3]);
        float* op = g_xproj + (size_t)(m0 + tm * 4 + i) * 1024 + n0 + tn * 8;
        *(float4*)(op)     = make_float4(p0.x + bias0.x, p0.y + bias0.y,
                                         p1.x + bias0.z, p1.y + bias0.w);
        *(float4*)(op + 4) = make_float4(p2.x + bias1.x, p2.y + bias1.y,
                                         p3.x + bias1.z, p3.y + bias1.w);
    }
}

// ---------------------------------------------------------------------------
// Phase 2: dual-group pipelined recurrence (R9 + B-send race fix).
// ---------------------------------------------------------------------------
#define RSTRIDE 132
#define HBUFSZ  (8 * RSTRIDE)

__global__ __launch_bounds__(256, 1) __cluster_dims__(8, 1, 1)
void lstm_rec(const float* __restrict__ Wh, float* __restrict__ out) {
    __shared__ __align__(16) float hbuf[2][2][HBUFSZ];   // [group][buf]
    __shared__ __align__(16) float stage[2][2][128];     // [group][buf]
    __shared__ __align__(8)  ull   mbars[4];             // [group*2+buf]

    const int tid  = threadIdx.x;
    const int lane = tid & 31;
    const int w    = tid >> 5;
    const int s    = lane >> 3;
    const int cl   = lane & 7;
    const int m    = cl >> 1;
    const int q    = cl & 1;

    uint32_t rank;
    asm("mov.u32 %0, %%cluster_ctarank;" : "=r"(rank));
    const int r     = (int)rank;
    const int b0A   = (blockIdx.x >> 3) * 8;
    const int b0B   = b0A + 4;
    const int j     = w * 4 + m;
    const int koff  = r * 32 + j;
    const int colg0 = (2 * q) * 256 + koff;
    const int colg1 = (2 * q + 1) * 256 + koff;
    const int kbase = s * 64;

    ull wreg0[32], wreg1[32];
#pragma unroll
    for (int i = 0; i < 32; ++i) {
        const float* p0 = Wh + (size_t)(kbase + 2 * i) * 1024;
        const float* p1 = Wh + (size_t)(kbase + 2 * i + 1) * 1024;
        wreg0[i] = pack2(__ldg(p0 + colg0), __ldg(p1 + colg0));
        wreg1[i] = pack2(__ldg(p0 + colg1), __ldg(p1 + colg1));
    }

    for (int i = tid; i < 4 * HBUFSZ; i += 256) ((float*)hbuf)[i] = 0.0f;
    const uint32_t lmb = smem_u32(mbars);
    if (tid == 0) {
#pragma unroll
        for (int i = 0; i < 4; ++i)
            asm volatile("mbarrier.init.shared.b64 [%0], 1;"
                         :: "r"(lmb + 8 * i) : "memory");
    }
    __syncthreads();
    asm volatile("barrier.cluster.arrive.aligned;" ::: "memory");
    asm volatile("barrier.cluster.wait.aligned;"   ::: "memory");

    // remote addresses for sender lanes of warps 0 (group A) and 1 (group B)
    const uint32_t hbase = smem_u32(hbuf);
    const uint32_t sbase = smem_u32(stage);
    uint32_t rem_h = 0, rem_m = 0;
    if (w < 2 && lane < 8) {
        asm("mapa.shared::cluster.u32 %0, %1, %2;" : "=r"(rem_h) : "r"(hbase), "r"(lane));
        asm("mapa.shared::cluster.u32 %0, %1, %2;" : "=r"(rem_m) : "r"(lmb),   "r"(lane));
    }

    const float am0 = q ? 2.0f : 1.0f;
    const float om0 = q ? 2.0f : 1.0f;
    const float ob0 = q ? -1.0f : 0.0f;

    const bool cellw = (q == 0);
    const int  wslot = w * 16 + s * 4 + m;

    const float* xpA0 = g_xproj + (size_t)(b0A + s) * 512 * 1024 + colg0;
    const float* xpA1 = g_xproj + (size_t)(b0A + s) * 512 * 1024 + colg1;
    const float* xpB0 = g_xproj + (size_t)(b0B + s) * 512 * 1024 + colg0;
    const float* xpB1 = g_xproj + (size_t)(b0B + s) * 512 * 1024 + colg1;
    float* outA = out + (size_t)(b0A + s) * 512 * 256 + koff;
    float* outB = out + (size_t)(b0B + s) * 512 * 256 + koff;

    float xcA0 = __ldg(xpA0), xcA1 = __ldg(xpA1);
    float xcB0 = __ldg(xpB0), xcB1 = __ldg(xpB1);
    float creA = 0.0f, creB = 0.0f, hlA = 0.0f, hlB = 0.0f;

    auto dot_cell = [&](const float* hb, float xp0, float xp1,
                        float& cre) -> float {
        ull A00 = 0, A01 = 0, A02 = 0, A03 = 0;
        ull A10 = 0, A11 = 0, A12 = 0, A13 = 0;
#pragma unroll
        for (int rr = 0; rr < 2; ++rr) {
            const float* rbase = hb + (2 * s + rr) * RSTRIDE;
#pragma unroll
            for (int j4 = 0; j4 < 8; ++j4) {
                const float* qp = rbase + j4 * 16;
                ulonglong2 v0 = *(const ulonglong2*)(qp + 0);
                ulonglong2 v1 = *(const ulonglong2*)(qp + 4);
                ulonglong2 v2 = *(const ulonglong2*)(qp + 8);
                ulonglong2 v3 = *(const ulonglong2*)(qp + 12);
                const int iw = rr * 16 + j4 * 2;
                fma2(A00, wreg0[iw], v0.x); fma2(A00, wreg0[iw + 1], v0.y);
                fma2(A01, wreg0[iw], v1.x); fma2(A01, wreg0[iw + 1], v1.y);
                fma2(A02, wreg0[iw], v2.x); fma2(A02, wreg0[iw + 1], v2.y);
                fma2(A03, wreg0[iw], v3.x); fma2(A03, wreg0[iw + 1], v3.y);
                fma2(A10, wreg1[iw], v0.x); fma2(A10, wreg1[iw + 1], v0.y);
                fma2(A11, wreg1[iw], v1.x); fma2(A11, wreg1[iw + 1], v1.y);
                fma2(A12, wreg1[iw], v2.x); fma2(A12, wreg1[iw + 1], v2.y);
                fma2(A13, wreg1[iw], v3.x); fma2(A13, wreg1[iw + 1], v3.y);
            }
        }
        float2 p;
        float d00, d01, d02, d03, d10, d11, d12, d13;
        p = unpack2(A00); d00 = p.x + p.y;
        p = unpack2(A01); d01 = p.x + p.y;
        p = unpack2(A02); d02 = p.x + p.y;
        p = unpack2(A03); d03 = p.x + p.y;
        p = unpack2(A10); d10 = p.x + p.y;
        p = unpack2(A11); d11 = p.x + p.y;
        p = unpack2(A12); d12 = p.x + p.y;
        p = unpack2(A13); d13 = p.x + p.y;

        d00 += __shfl_xor_sync(0xffffffffu, d00, 8);
        d01 += __shfl_xor_sync(0xffffffffu, d01, 8);
        d02 += __shfl_xor_sync(0xffffffffu, d02, 8);
        d03 += __shfl_xor_sync(0xffffffffu, d03, 8);
        d10 += __shfl_xor_sync(0xffffffffu, d10, 8);
        d11 += __shfl_xor_sync(0xffffffffu, d11, 8);
        d12 += __shfl_xor_sync(0xffffffffu, d12, 8);
        d13 += __shfl_xor_sync(0xffffffffu, d13, 8);
        d00 += __shfl_xor_sync(0xffffffffu, d00, 16);
        d01 += __shfl_xor_sync(0xffffffffu, d01, 16);
        d02 += __shfl_xor_sync(0xffffffffu, d02, 16);
        d03 += __shfl_xor_sync(0xffffffffu, d03, 16);
        d10 += __shfl_xor_sync(0xffffffffu, d10, 16);
        d11 += __shfl_xor_sync(0xffffffffu, d11, 16);
        d12 += __shfl_xor_sync(0xffffffffu, d12, 16);
        d13 += __shfl_xor_sync(0xffffffffu, d13, 16);

        float ds0 = (s == 0) ? d00 : (s == 1) ? d01 : (s == 2) ? d02 : d03;
        float ds1 = (s == 0) ? d10 : (s == 1) ? d11 : (s == 2) ? d12 : d13;
        float gx0 = xp0 + ds0;
        float gx1 = xp1 + ds1;

        float u0 = __expf(-am0 * gx0);
        float e0 = fmaf(rcpf(1.0f + u0), om0, ob0);
        float u1 = __expf(-gx1);
        float e1 = rcpf(1.0f + u1);

        float gg = __shfl_xor_sync(0xffffffffu, e0, 1);
        float oo = __shfl_xor_sync(0xffffffffu, e1, 1);

        float hn = 0.0f;
        if (cellw) {
            cre = fmaf(e1, cre, e0 * gg);
            float u2 = __expf(-2.0f * cre);
            float th = (1.0f - u2) * rcpf(1.0f + u2);
            hn = oo * th;
        }
        return hn;
    };

    auto wait_mbar = [&](int g, int u) {
        uint32_t mw = lmb + (uint32_t)((g * 2 + (u & 1)) << 3);
        uint32_t pr = (uint32_t)((u >> 1) & 1);
        asm volatile(
            "{\n\t.reg .pred P;\n"
            "W_%=:\n\t"
            "mbarrier.try_wait.parity.acquire.cta.shared::cta.b64 P, [%0], %1, 0x989680;\n\t"
            "@P bra.uni D_%=;\n\t"
            "bra.uni W_%=;\n\t"
            "D_%=:\n\t}"
            :: "r"(mw), "r"(pr) : "memory");
    };

    auto send_group = [&](int g, int t) {   // caller gates on warp & lane
        asm volatile("fence.proxy.async.shared::cta;" ::: "memory");
        uint32_t idx = (uint32_t)(g * 2 + (t & 1));
        uint32_t src = sbase + idx * 512u;
        uint32_t dst = rem_h + (uint32_t)((idx * HBUFSZ + r * RSTRIDE) * 4);
        uint32_t mba = rem_m + (idx << 3);
        asm volatile(
            "cp.async.bulk.shared::cluster.shared::cta.mbarrier::complete_tx::bytes "
            "[%0], [%1], %2, [%3];"
            :: "r"(dst), "r"(src), "r"(512u), "r"(mba) : "memory");
    };

#pragma unroll 1
    for (int t = 0; t < 512; ++t) {
        // ================= group A =================
        if (t > 0) wait_mbar(0, t - 1);
        if (tid == 0 && t < 511) {
            uint32_t ma = lmb + (uint32_t)((t & 1) << 3);
            asm volatile("mbarrier.arrive.expect_tx.shared.b64 _, [%0], %1;"
                         :: "r"(ma), "r"(4096u) : "memory");
        }
        {
            const float* hb = (const float*)hbuf + ((t + 1) & 1) * HBUFSZ;
            float hn = dot_cell(hb, xcA0, xcA1, creA);
            if (cellw) { hlA = hn; stage[0][t & 1][wslot] = hn; }

            if (w == 0) asm volatile("bar.sync 1, 256;" ::: "memory");
            else        asm volatile("bar.arrive 1, 256;" ::: "memory");

            if (t < 511 && w == 0 && lane < 8) send_group(0, t);

            if (cellw) outA[(size_t)t * 256] = hn;
            if (t < 511) { xcA0 = __ldg(xpA0 + (size_t)(t + 1) * 1024);
                           xcA1 = __ldg(xpA1 + (size_t)(t + 1) * 1024); }
        }

        // ================= group B =================
        if (t > 0) wait_mbar(1, t - 1);
        if (tid == 0 && t < 511) {
            uint32_t ma = lmb + (uint32_t)((2 + (t & 1)) << 3);
            asm volatile("mbarrier.arrive.expect_tx.shared.b64 _, [%0], %1;"
                         :: "r"(ma), "r"(4096u) : "memory");
        }
        {
            const float* hb = (const float*)hbuf + (2 + ((t + 1) & 1)) * HBUFSZ;
            float hn = dot_cell(hb, xcB0, xcB1, creB);
            if (cellw) { hlB = hn; stage[1][t & 1][wslot] = hn; }

            if (w == 1) asm volatile("bar.sync 2, 256;" ::: "memory");
            else        asm volatile("bar.arrive 2, 256;" ::: "memory");

            // fix: B-send from warp 1 (the warp that bar.sync'd barrier 2)
            if (t < 511 && w == 1 && lane < 8) send_group(1, t);

            if (cellw) outB[(size_t)t * 256] = hn;
            if (t < 511) { xcB0 = __ldg(xpB0 + (size_t)(t + 1) * 1024);
                           xcB1 = __ldg(xpB1 + (size_t)(t + 1) * 1024); }
        }
    }

    if (cellw) {
        out[8388608u + (size_t)(b0A + s) * 256 + koff]          = hlA;
        out[8388608u + 16384u + (size_t)(b0A + s) * 256 + koff] = creA;
        out[8388608u + (size_t)(b0B + s) * 256 + koff]          = hlB;
        out[8388608u + 16384u + (size_t)(b0B + s) * 256 + koff] = creB;
    }
}

// ---------------------------------------------------------------------------
extern "C" void kernel_launch(void* const* d_in, const int* in_sizes, int n_in,
                              void* d_out, int out_size) {
    const float* x  = nullptr;   // 64*512*128 = 4194304
    const float* Wi = nullptr;   // 128*1024   = 131072
    const float* Wh = nullptr;   // 256*1024   = 262144
    const float* Bb = nullptr;   // 1024
    for (int i = 0; i < n_in; ++i) {
        switch (in_sizes[i]) {
            case 4194304: x  = (const float*)d_in[i]; break;
            case 131072:  Wi = (const float*)d_in[i]; break;
            case 262144:  Wh = (const float*)d_in[i]; break;
            case 1024:    Bb = (const float*)d_in[i]; break;
            default: break;
        }
    }
    float* out = (float*)d_out;
    (void)out_size;

    xproj_kernel<<<dim3(8, 512), 256>>>(x, Wi, Bb);
    lstm_rec<<<64, 256>>>(Wh, out);
}